// round 6
// baseline (speedup 1.0000x reference)
#include <cuda_runtime.h>
#include <cstdint>

// HOG fused kernel R6: 2x2-quad deduplicated 4-way histogram RMW, load-ahead
// pipeline, float-pipe classification, prefix histogram.
// x: (64,1,512,512) f32. out: (64, 9*64*64) f32.
// Block = (image n, cell-row cy) stripe, 256 threads: cell = t/4, sub = t%4 (2 rows).
// Tile: col c -> 10*(c>>3) + (c&7) + 4 (cell stride 10, conflict-free); idx1/idx644 halos.

#define TS2 646

__device__ __forceinline__ uint32_t smem_u32(const void* p)
{
    uint32_t a;
    asm("{ .reg .u64 t; cvta.to.shared.u64 t, %1; cvt.u32.u64 %0, t; }"
        : "=r"(a) : "l"(p));
    return a;
}

__device__ __forceinline__ float setge(float a, float b)
{
    float r;
    asm("set.ge.f32.f32 %0, %1, %2;" : "=f"(r) : "f"(a), "f"(b));
    return r;
}

// smem byte address of slot fl9 = floor(atan2(gx,gy)*9/pi)+9 in this thread's column
__device__ __forceinline__ uint32_t hog_class(float gx, float gy, uint32_t hb, float& mag)
{
    float d2 = fmaf(gx, gx, gy * gy);
    asm("sqrt.approx.f32 %0, %1;" : "=f"(mag) : "f"(d2));

    float u = fabsf(gx), v = fabsf(gy);
    float fa = (setge(u, 0.36397023f * v) + setge(u, 0.83909963f * v))
             + (setge(u, 1.73205081f * v) + setge(u, 5.67128182f * v));  // 0..4

    uint32_t bx = __float_as_uint(gx), by = __float_as_uint(gy);
    uint32_t xo = bx ^ by;
    float negfa = __uint_as_float(__float_as_uint(fa) ^ (xo & 0x80000000u));
    float cf = ((int)bx < 0) ? (((int)xo < 0) ? 8.0f : 0.0f)
                             : (((int)xo < 0) ? 17.0f : 9.0f);
    float m = (cf + negfa) + 12582912.0f;        // 0x4B400000 + fl9 (exact)
    return hb + (__float_as_uint(m) << 10);
}

// 4 histogram updates, duplicates merged to earliest slot, surviving RMW
// chains fully overlapped (all LDS before any STS; distinct addrs guaranteed).
__device__ __forceinline__ void emit4(uint32_t a0, float m0, uint32_t a1, float m1,
                                      uint32_t a2, float m2, uint32_t a3, float m3)
{
    asm volatile(
        "{\n\t"
        ".reg .pred q10,q20,q21,q30,q31,q32,v1,v2,v3,t2,t3,nn;\n\t"
        ".reg .f32 r0,r1,r2,r3;\n\t"
        // pixel1 vs pixel0
        "setp.eq.u32 q10, %5, %4;\n\t"
        "@q10 add.f32 %0, %0, %1;\n\t"
        "not.pred v1, q10;\n\t"
        // pixel2 vs {0,1}
        "setp.eq.u32 q20, %6, %4;\n\t"
        "@q20 add.f32 %0, %0, %2;\n\t"
        "setp.eq.u32 q21, %6, %5;\n\t"
        "not.pred nn, q20;\n\t"
        "and.pred t2, q21, nn;\n\t"
        "@t2 add.f32 %1, %1, %2;\n\t"
        "or.pred q20, q20, q21;\n\t"
        "not.pred v2, q20;\n\t"
        // pixel3 vs {0,1,2}
        "setp.eq.u32 q30, %7, %4;\n\t"
        "@q30 add.f32 %0, %0, %3;\n\t"
        "setp.eq.u32 q31, %7, %5;\n\t"
        "not.pred nn, q30;\n\t"
        "and.pred t3, q31, nn;\n\t"
        "@t3 add.f32 %1, %1, %3;\n\t"
        "setp.eq.u32 q32, %7, %6;\n\t"
        "or.pred q30, q30, q31;\n\t"
        "not.pred nn, q30;\n\t"
        "and.pred t3, q32, nn;\n\t"
        "@t3 add.f32 %2, %2, %3;\n\t"
        "or.pred q30, q30, q32;\n\t"
        "not.pred v3, q30;\n\t"
        // overlapped RMW chains
        "ld.shared.f32 r0, [%4];\n\t"
        "@v1 ld.shared.f32 r1, [%5];\n\t"
        "@v2 ld.shared.f32 r2, [%6];\n\t"
        "@v3 ld.shared.f32 r3, [%7];\n\t"
        "add.f32 r0, r0, %0;\n\t"
        "@v1 add.f32 r1, r1, %1;\n\t"
        "@v2 add.f32 r2, r2, %2;\n\t"
        "@v3 add.f32 r3, r3, %3;\n\t"
        "st.shared.f32 [%4], r0;\n\t"
        "@v1 st.shared.f32 [%5], r1;\n\t"
        "@v2 st.shared.f32 [%6], r2;\n\t"
        "@v3 st.shared.f32 [%7], r3;\n\t"
        "}"
        : "+f"(m0), "+f"(m1), "+f"(m2), "+f"(m3)
        : "r"(a0), "r"(a1), "r"(a2), "r"(a3)
        : "memory");
}

__device__ __forceinline__ void quad(uint32_t hb,
                                     float gxa, float gya, float gxb, float gyb,
                                     float gxc, float gyc, float gxd, float gyd)
{
    float m0, m1, m2, m3;
    uint32_t a0 = hog_class(gxa, gya, hb, m0);
    uint32_t a1 = hog_class(gxb, gyb, hb, m1);
    uint32_t a2 = hog_class(gxc, gyc, hb, m2);
    uint32_t a3 = hog_class(gxd, gyd, hb, m3);
    emit4(a0, m0, a1, m1, a2, m2, a3, m3);
}

__global__ __launch_bounds__(256, 5)
void hog_kernel(const float* __restrict__ x, float* __restrict__ out)
{
    __shared__ __align__(16) float tile[10 * TS2];
    __shared__ float hist[18 * 256];

    const int tid = threadIdx.x;
    const int n   = blockIdx.x >> 6;
    const int cy  = blockIdx.x & 63;

#pragma unroll
    for (int b = 0; b < 18; ++b) hist[b * 256 + tid] = 0.0f;

    // ---- load 10 rows into padded tile ----
    const float* img  = x + (size_t)n * (512 * 512);
    const int    row0 = cy * 8 - 1;
#pragma unroll
    for (int i = 0; i < 5; ++i) {
        int idx = tid + i * 256;
        int r   = idx >> 7;
        int k   = idx & 127;
        int gr  = row0 + r;
        float4 v = make_float4(0.f, 0.f, 0.f, 0.f);
        if ((unsigned)gr < 512u)
            v = *reinterpret_cast<const float4*>(img + (size_t)gr * 512 + k * 4);
        float* d = &tile[r * TS2 + 5 * k + 4 - (k & 1)];
        *reinterpret_cast<float2*>(d)     = make_float2(v.x, v.y);
        *reinterpret_cast<float2*>(d + 2) = make_float2(v.z, v.w);
    }
    if (tid < 10) { tile[tid * TS2 + 1] = 0.f; tile[tid * TS2 + 644] = 0.f; }
    __syncthreads();

    // ---- mainloop: 2x2 quads, loads ahead of emits ----
    const int cell = tid >> 2;
    const int sub  = tid & 3;
    const float* pw = &tile[(2 * sub + 0) * TS2 + 10 * cell];
    const float* pa = &tile[(2 * sub + 1) * TS2 + 10 * cell];
    const float* pb = &tile[(2 * sub + 2) * TS2 + 10 * cell];
    const float* pc = &tile[(2 * sub + 3) * TS2 + 10 * cell];
    const uint32_t hb = smem_u32(&hist[tid]);

    // state: scalars at col 2k-1, float2 at (2k,2k+1), vertical sums
    float wm = pw[1], am = pa[1], bm = pb[1], cm = pc[1];   // col -1 halo
    float2 wp = *reinterpret_cast<const float2*>(pw + 4);
    float2 ap = *reinterpret_cast<const float2*>(pa + 4);
    float2 bp = *reinterpret_cast<const float2*>(pb + 4);
    float2 cp = *reinterpret_cast<const float2*>(pc + 4);

    float Am = wm + 2.f * am + bm;
    float Bm = am + 2.f * bm + cm;
    float A0 = wp.x + 2.f * ap.x + bp.x, A1 = wp.y + 2.f * ap.y + bp.y;
    float B0 = ap.x + 2.f * bp.x + cp.x, B1 = ap.y + 2.f * bp.y + cp.y;

#pragma unroll
    for (int k = 0; k < 3; ++k) {
        float2 wn = *reinterpret_cast<const float2*>(pw + 6 + 2 * k);
        float2 an = *reinterpret_cast<const float2*>(pa + 6 + 2 * k);
        float2 bn = *reinterpret_cast<const float2*>(pb + 6 + 2 * k);
        float2 cn = *reinterpret_cast<const float2*>(pc + 6 + 2 * k);
        float A2 = wn.x + 2.f * an.x + bn.x, A3 = wn.y + 2.f * an.y + bn.y;
        float B2 = an.x + 2.f * bn.x + cn.x, B3 = an.y + 2.f * bn.y + cn.y;

        quad(hb,
             // (row0, col 2k)        (row1, col 2k)
             Am - A1, (wm + 2.f * wp.x + wp.y) - (bm + 2.f * bp.x + bp.y),
             Bm - B1, (am + 2.f * ap.x + ap.y) - (cm + 2.f * cp.x + cp.y),
             // (row0, col 2k+1)      (row1, col 2k+1)
             A0 - A2, (wp.x + 2.f * wp.y + wn.x) - (bp.x + 2.f * bp.y + bn.x),
             B0 - B2, (ap.x + 2.f * ap.y + an.x) - (cp.x + 2.f * cp.y + cn.x));

        wm = wp.y; am = ap.y; bm = bp.y; cm = cp.y;
        wp = wn; ap = an; bp = bn; cp = cn;
        Am = A1; A0 = A2; A1 = A3;
        Bm = B1; B0 = B2; B1 = B3;
    }

    // tail: cols 6,7 with right halo col 8 (scalar at offset 14)
    {
        float rw = pw[14], ra = pa[14], rb = pb[14], rc = pc[14];
        float A8 = rw + 2.f * ra + rb;
        float B8 = ra + 2.f * rb + rc;
        quad(hb,
             Am - A1, (wm + 2.f * wp.x + wp.y) - (bm + 2.f * bp.x + bp.y),
             Bm - B1, (am + 2.f * ap.x + ap.y) - (cm + 2.f * cp.x + cp.y),
             A0 - A8, (wp.x + 2.f * wp.y + rw) - (bp.x + 2.f * bp.y + rb),
             B0 - B8, (ap.x + 2.f * ap.y + ra) - (cp.x + 2.f * cp.y + rc));
    }

    asm volatile("" ::: "memory");

    // ---- fold P -> 9 bins in registers, shuffle-reduce 4 subs, write ----
    float P[18];
#pragma unroll
    for (int s = 0; s < 18; ++s) P[s] = hist[s * 256 + tid];
    float bin[9];
    bin[0] = (P[0] + P[8]) + (P[9] + P[17]);
#pragma unroll
    for (int b = 1; b < 9; ++b) bin[b] = (P[b - 1] + P[b]) + (P[b + 8] + P[b + 9]);

#pragma unroll
    for (int b = 0; b < 9; ++b) {
        bin[b] += __shfl_xor_sync(0xffffffffu, bin[b], 1);
        bin[b] += __shfl_xor_sync(0xffffffffu, bin[b], 2);
    }

    if (sub == 0) {
        float* o = out + (size_t)n * 36864 + cy * 64 + cell;
#pragma unroll
        for (int b = 0; b < 9; ++b)
            o[(size_t)b * 4096] = bin[b] * 0.015625f;   // 1/64
    }
}

extern "C" void kernel_launch(void* const* d_in, const int* in_sizes, int n_in,
                              void* d_out, int out_size)
{
    const float* x = (const float*)d_in[0];
    float* out = (float*)d_out;
    (void)in_sizes; (void)n_in; (void)out_size;
    hog_kernel<<<4096, 256>>>(x, out);
}